// round 1
// baseline (speedup 1.0000x reference)
#include <cuda_runtime.h>
#include <math.h>

// ---------------- problem constants ----------------
#define Bsz     2
#define Hdim    256
#define Wdim    256
#define Cc      192
#define NHEADS  6
#define HEADDIM 32
#define HID     768
#define TOK     (Bsz*Hdim*Wdim)      // 131072 tokens
#define NWINY   32
#define NWINX   32
#define NWIN    (Bsz*NWINY*NWINX)    // 2048 windows

// ---------------- scratch (device globals: no cudaMalloc allowed) ----------------
__device__ float g_bufA[(size_t)TOK*Cc];    // xn / xn2
__device__ float g_bufB[(size_t)TOK*Cc];    // attention output (pre-proj)
__device__ float g_bufC[(size_t)TOK*Cc];    // x after attention residual
__device__ float g_bufD[(size_t)TOK*HID];   // q, later h1
__device__ float g_bufE[(size_t)TOK*HID];   // kv, later h

__device__ __forceinline__ float gelu_exact(float x) {
    return 0.5f * x * (1.0f + erff(x * 0.70710678118654752f));
}

// ---------------- LayerNorm: one warp per token ----------------
__global__ __launch_bounds__(256)
void ln_kernel(const float* __restrict__ x, const float* __restrict__ g,
               const float* __restrict__ b, float* __restrict__ out) {
    int warp = (blockIdx.x * blockDim.x + threadIdx.x) >> 5;
    int lane = threadIdx.x & 31;
    if (warp >= TOK) return;
    const float* xr = x + (size_t)warp * Cc;
    float v[6];
    float s = 0.f, s2 = 0.f;
#pragma unroll
    for (int j = 0; j < 6; j++) {
        v[j] = xr[lane + 32*j];
        s += v[j]; s2 += v[j]*v[j];
    }
#pragma unroll
    for (int o = 16; o; o >>= 1) {
        s  += __shfl_xor_sync(0xffffffffu, s,  o);
        s2 += __shfl_xor_sync(0xffffffffu, s2, o);
    }
    float mu  = s  * (1.f/Cc);
    float var = s2 * (1.f/Cc) - mu*mu;
    float r   = rsqrtf(var + 1e-5f);
    float* orow = out + (size_t)warp * Cc;
#pragma unroll
    for (int j = 0; j < 6; j++) {
        int c = lane + 32*j;
        orow[c] = (v[j]-mu)*r*g[c] + b[c];
    }
}

// ---------------- generic tiled SGEMM: C = A[M,K] @ W[K,N] (+bias)(+gelu)(+res) ----------------
// EPI: 0=plain, 1=bias, 2=bias+gelu, 3=bias+residual
template<int EPI>
__global__ __launch_bounds__(256)
void gemm_kernel(const float* __restrict__ A, const float* __restrict__ Wt,
                 const float* __restrict__ bias, const float* __restrict__ res,
                 float* __restrict__ C, int M, int N, int K) {
    __shared__ float As[16][65];   // [k][row], padded
    __shared__ float Bs[16][64];   // [k][col]
    const int tid = threadIdx.x;
    const int m0 = blockIdx.y * 64;
    const int n0 = blockIdx.x * 64;

    const int arow = tid >> 2;            // 0..63
    const int akf  = (tid & 3) * 4;       // 0,4,8,12
    const int bk   = tid >> 4;            // 0..15
    const int bn   = (tid & 15) * 4;      // 0..60

    const int r0 = (tid >> 4) * 4;        // compute rows
    const int c0 = (tid & 15) * 4;        // compute cols

    float acc[4][4];
#pragma unroll
    for (int i = 0; i < 4; i++)
#pragma unroll
        for (int j = 0; j < 4; j++) acc[i][j] = 0.f;

    for (int k0 = 0; k0 < K; k0 += 16) {
        float4 a4 = *(const float4*)(A + (size_t)(m0 + arow)*K + k0 + akf);
        As[akf+0][arow] = a4.x; As[akf+1][arow] = a4.y;
        As[akf+2][arow] = a4.z; As[akf+3][arow] = a4.w;
        float4 b4 = make_float4(0.f,0.f,0.f,0.f);
        if (n0 + bn < N)
            b4 = *(const float4*)(Wt + (size_t)(k0 + bk)*N + n0 + bn);
        *(float4*)&Bs[bk][bn] = b4;
        __syncthreads();
#pragma unroll
        for (int kk = 0; kk < 16; kk++) {
            float4 bb = *(float4*)&Bs[kk][c0];
            float a0 = As[kk][r0+0], a1 = As[kk][r0+1];
            float a2 = As[kk][r0+2], a3 = As[kk][r0+3];
            acc[0][0] += a0*bb.x; acc[0][1] += a0*bb.y; acc[0][2] += a0*bb.z; acc[0][3] += a0*bb.w;
            acc[1][0] += a1*bb.x; acc[1][1] += a1*bb.y; acc[1][2] += a1*bb.z; acc[1][3] += a1*bb.w;
            acc[2][0] += a2*bb.x; acc[2][1] += a2*bb.y; acc[2][2] += a2*bb.z; acc[2][3] += a2*bb.w;
            acc[3][0] += a3*bb.x; acc[3][1] += a3*bb.y; acc[3][2] += a3*bb.z; acc[3][3] += a3*bb.w;
        }
        __syncthreads();
    }
#pragma unroll
    for (int i = 0; i < 4; i++) {
        int row = m0 + r0 + i;
#pragma unroll
        for (int j = 0; j < 4; j++) {
            int col = n0 + c0 + j;
            if (col < N) {
                float v = acc[i][j];
                if (EPI >= 1) v += bias[col];
                if (EPI == 2) v = gelu_exact(v);
                if (EPI == 3) v += res[(size_t)row*N + col];
                C[(size_t)row*N + col] = v;
            }
        }
    }
}

// ---------------- fused windowed attention (per-window block) ----------------
// qbuf:  (TOK, 192) token-major; kvbuf: (TOK, 96) token-major
// thread = (head, qtoken): 6*64 = 384 threads
__global__ __launch_bounds__(384)
void attn_kernel(const float* __restrict__ qbuf, const float* __restrict__ kvbuf,
                 const float* __restrict__ bias_table, float* __restrict__ aw) {
    __shared__ float sk[NHEADS*16*32];
    __shared__ float sv[NHEADS*16*32];
    const int wid = blockIdx.x;
    const int b  = wid >> 10;
    const int wy = (wid >> 5) & 31;
    const int wx = wid & 31;
    const int base = b*65536 + wy*8*256 + wx*8;   // token row of window origin
    const int tid = threadIdx.x;

    // gather + PSA-rearrange K,V into smem: k/v[h][kvtok][d]
    for (int ii = tid; ii < 2*16*192; ii += 384) {
        int sel = ii / (16*192);
        int rem = ii - sel*(16*192);
        int tok = rem / 192;           // kv token (p1*4+p2)
        int hd  = rem - tok*192;       // h*32+d
        int i   = hd / 96;
        int j   = (hd / 48) & 1;
        int c48 = hd % 48;
        int p1 = tok >> 2, p2 = tok & 3;
        int grow = base + (p1*2 + i)*256 + (p2*2 + j);
        float val = kvbuf[(size_t)grow*96 + sel*48 + c48];
        float* dst = sel ? sv : sk;
        dst[(hd >> 5)*512 + tok*32 + (hd & 31)] = val;
    }
    __syncthreads();

    const int h  = tid / 64;
    const int qt = tid % 64;
    const int qr = qt >> 3, qc = qt & 7;
    const int qrow = base + qr*256 + qc;

    float q[32];
    const float* qp = qbuf + (size_t)qrow*Cc + h*32;
#pragma unroll
    for (int d4 = 0; d4 < 8; d4++) {
        float4 t = *(const float4*)(qp + d4*4);
        q[d4*4+0]=t.x; q[d4*4+1]=t.y; q[d4*4+2]=t.z; q[d4*4+3]=t.w;
    }

    const float SCALE = 0.17677669529663687f;   // 32^-0.5
    const int qr2 = qr >> 1, qc2 = qc >> 1;
    float sc[16];
    float m = -1e30f;
#pragma unroll
    for (int kv = 0; kv < 16; kv++) {
        const float* kp = sk + h*512 + kv*32;
        float dot = 0.f;
#pragma unroll
        for (int d = 0; d < 32; d++) dot += q[d]*kp[d];
        int kr = kv >> 2, kc = kv & 3;
        int rel = (qr2 - kr + 3)*7 + (qc2 - kc + 3);
        float s = dot*SCALE + bias_table[rel*NHEADS + h];
        sc[kv] = s;
        m = fmaxf(m, s);
    }
    float sum = 0.f;
#pragma unroll
    for (int kv = 0; kv < 16; kv++) { sc[kv] = expf(sc[kv]-m); sum += sc[kv]; }
    float inv = 1.f/sum;
    float o[32];
#pragma unroll
    for (int d = 0; d < 32; d++) o[d] = 0.f;
#pragma unroll
    for (int kv = 0; kv < 16; kv++) {
        float p = sc[kv]*inv;
        const float* vp = sv + h*512 + kv*32;
#pragma unroll
        for (int d = 0; d < 32; d++) o[d] += p*vp[d];
    }
    float* op = aw + (size_t)qrow*Cc + h*32;
#pragma unroll
    for (int d4 = 0; d4 < 8; d4++) {
        *(float4*)(op + d4*4) = make_float4(o[d4*4+0],o[d4*4+1],o[d4*4+2],o[d4*4+3]);
    }
}

// ---------------- depthwise 5x5 conv branch: out = h1 + gelu(dwconv(h1)+dwb) ----------------
// h1: (TOK, 768) token-major. Block: 8x8 pixel tile x 64 channels; 256 threads.
__global__ __launch_bounds__(256)
void dwconv_kernel(const float* __restrict__ h1, const float* __restrict__ dwk,
                   const float* __restrict__ dwb, float* __restrict__ out) {
    __shared__ float2 s[144][32];      // 12x12 pixels x 32 channel-pairs
    const int cb = blockIdx.z % 12;    // channel block (64 ch)
    const int b  = blockIdx.z / 12;
    const int y0 = blockIdx.y * 8, x0 = blockIdx.x * 8;
    const int tid = threadIdx.x;

    for (int ii = tid; ii < 144*32; ii += 256) {
        int pix = ii >> 5, c2 = ii & 31;
        int py = pix / 12, px = pix % 12;
        int gy = y0 + py - 2, gx = x0 + px - 2;
        float2 v = make_float2(0.f, 0.f);
        if (gy >= 0 && gy < Hdim && gx >= 0 && gx < Wdim) {
            size_t row = (size_t)(b*65536 + gy*256 + gx);
            v = *(const float2*)(h1 + row*HID + cb*64 + c2*2);
        }
        s[pix][c2] = v;
    }
    __syncthreads();

    const int c2 = tid & 31;
    const int pq = tid >> 5;           // pixel row within tile (0..7)
    const int c0 = cb*64 + c2*2;

    float2 wk[25];
#pragma unroll
    for (int t = 0; t < 25; t++) {
        wk[t].x = dwk[(size_t)c0*25 + t];
        wk[t].y = dwk[(size_t)(c0+1)*25 + t];
    }
    float2 bb = make_float2(dwb[c0], dwb[c0+1]);

    // sliding 5x5 register window over px
    float2 win[5][5];  // [dx][dy]
#pragma unroll
    for (int dx = 0; dx < 5; dx++)
#pragma unroll
        for (int dy = 0; dy < 5; dy++)
            win[dx][dy] = s[(pq+dy)*12 + dx][c2];

#pragma unroll
    for (int px = 0; px < 8; px++) {
        float2 acc = make_float2(0.f, 0.f);
#pragma unroll
        for (int dy = 0; dy < 5; dy++)
#pragma unroll
            for (int dx = 0; dx < 5; dx++) {
                float2 v = win[dx][dy];
                float2 w = wk[dy*5+dx];
                acc.x += v.x*w.x;
                acc.y += v.y*w.y;
            }
        float2 center = win[2][2];   // h1 at this pixel
        float2 r;
        r.x = center.x + gelu_exact(acc.x + bb.x);
        r.y = center.y + gelu_exact(acc.y + bb.y);
        size_t row = (size_t)(b*65536 + (y0+pq)*256 + (x0+px));
        *(float2*)(out + row*HID + c0) = r;
        if (px < 7) {
#pragma unroll
            for (int dx = 0; dx < 4; dx++)
#pragma unroll
                for (int dy = 0; dy < 5; dy++)
                    win[dx][dy] = win[dx+1][dy];
#pragma unroll
            for (int dy = 0; dy < 5; dy++)
                win[4][dy] = s[(pq+dy)*12 + (px+5)][c2];
        }
    }
}

// ---------------- launch ----------------
extern "C" void kernel_launch(void* const* d_in, const int* in_sizes, int n_in,
                              void* d_out, int out_size) {
    const float* x          = (const float*)d_in[0];
    const float* g1         = (const float*)d_in[1];
    const float* be1        = (const float*)d_in[2];
    const float* wq         = (const float*)d_in[3];
    const float* bq         = (const float*)d_in[4];
    const float* wkv        = (const float*)d_in[5];
    const float* bkv        = (const float*)d_in[6];
    const float* bias_table = (const float*)d_in[7];
    const float* wproj      = (const float*)d_in[8];
    const float* bproj      = (const float*)d_in[9];
    const float* g2         = (const float*)d_in[10];
    const float* be2        = (const float*)d_in[11];
    const float* w1f        = (const float*)d_in[12];
    const float* b1f        = (const float*)d_in[13];
    const float* dwk        = (const float*)d_in[14];
    const float* dwb        = (const float*)d_in[15];
    const float* w2f        = (const float*)d_in[16];
    const float* b2f        = (const float*)d_in[17];
    float* out = (float*)d_out;

    float *bufA, *bufB, *bufC, *bufD, *bufE;
    cudaGetSymbolAddress((void**)&bufA, g_bufA);
    cudaGetSymbolAddress((void**)&bufB, g_bufB);
    cudaGetSymbolAddress((void**)&bufC, g_bufC);
    cudaGetSymbolAddress((void**)&bufD, g_bufD);
    cudaGetSymbolAddress((void**)&bufE, g_bufE);

    // 1. LN1: x -> xn (bufA)
    ln_kernel<<<TOK/8, 256>>>(x, g1, be1, bufA);

    // 2. q = xn @ wq + bq -> bufD   (M=TOK, N=192, K=192)
    gemm_kernel<1><<<dim3(3, TOK/64), 256>>>(bufA, wq, bq, nullptr, bufD, TOK, 192, 192);

    // 3. kv = xn @ wkv + bkv -> bufE   (N=96)
    gemm_kernel<1><<<dim3(2, TOK/64), 256>>>(bufA, wkv, bkv, nullptr, bufE, TOK, 96, 192);

    // 4. windowed attention -> bufB (token-major, pre-proj)
    attn_kernel<<<NWIN, 384>>>(bufD, bufE, bias_table, bufB);

    // 5. x2 = x + aw @ wproj + bproj -> bufC
    gemm_kernel<3><<<dim3(3, TOK/64), 256>>>(bufB, wproj, bproj, x, bufC, TOK, 192, 192);

    // 6. LN2: x2 -> xn2 (bufA)
    ln_kernel<<<TOK/8, 256>>>(bufC, g2, be2, bufA);

    // 7. h1 = gelu(xn2 @ w1f + b1f) -> bufD   (N=768)
    gemm_kernel<2><<<dim3(12, TOK/64), 256>>>(bufA, w1f, b1f, nullptr, bufD, TOK, HID, 192);

    // 8. h = h1 + gelu(dwconv(h1) + dwb) -> bufE
    dwconv_kernel<<<dim3(32, 32, Bsz*12), 256>>>(bufD, dwk, dwb, bufE);

    // 9. out = x2 + h @ w2f + b2f
    gemm_kernel<3><<<dim3(3, TOK/64), 256>>>(bufE, w2f, b2f, bufC, out, TOK, 192, HID);
}

// round 2
// speedup vs baseline: 1.5858x; 1.5858x over previous
#include <cuda_runtime.h>
#include <math.h>

// ---------------- problem constants ----------------
#define Bsz     2
#define Hdim    256
#define Wdim    256
#define Cc      192
#define NHEADS  6
#define HEADDIM 32
#define HID     768
#define TOK     (Bsz*Hdim*Wdim)      // 131072 tokens
#define NWIN    2048

// ---------------- scratch ----------------
__device__ float g_bufA[(size_t)TOK*Cc];
__device__ float g_bufB[(size_t)TOK*Cc];
__device__ float g_bufC[(size_t)TOK*Cc];
__device__ float g_bufD[(size_t)TOK*HID];
__device__ float g_bufE[(size_t)TOK*HID];

__device__ __forceinline__ float gelu_exact(float x) {
    return 0.5f * x * (1.0f + erff(x * 0.70710678118654752f));
}

__device__ __forceinline__ float to_tf32(float x) {
    float r;
    asm("cvt.rna.tf32.f32 %0, %1;" : "=f"(r) : "f"(x));
    return r;
}

// ---------------- LayerNorm ----------------
__global__ __launch_bounds__(256)
void ln_kernel(const float* __restrict__ x, const float* __restrict__ g,
               const float* __restrict__ b, float* __restrict__ out) {
    int warp = (blockIdx.x * blockDim.x + threadIdx.x) >> 5;
    int lane = threadIdx.x & 31;
    if (warp >= TOK) return;
    const float* xr = x + (size_t)warp * Cc;
    float v[6];
    float s = 0.f, s2 = 0.f;
#pragma unroll
    for (int j = 0; j < 6; j++) {
        v[j] = xr[lane + 32*j];
        s += v[j]; s2 += v[j]*v[j];
    }
#pragma unroll
    for (int o = 16; o; o >>= 1) {
        s  += __shfl_xor_sync(0xffffffffu, s,  o);
        s2 += __shfl_xor_sync(0xffffffffu, s2, o);
    }
    float mu  = s  * (1.f/Cc);
    float var = s2 * (1.f/Cc) - mu*mu;
    float r   = rsqrtf(var + 1e-5f);
    float* orow = out + (size_t)warp * Cc;
#pragma unroll
    for (int j = 0; j < 6; j++) {
        int c = lane + 32*j;
        orow[c] = (v[j]-mu)*r*g[c] + b[c];
    }
}

// ---------------- tf32 tensor-core GEMM ----------------
// C[M,N] = A[M,K] @ W[K,N]  (+bias)(+gelu)(+res)
// Block: 128x64 tile, 256 threads (8 warps as 4x2), warp tile 32x32.
// EPI: 1=bias, 2=bias+gelu, 3=bias+residual
#define BM 128
#define BN 64
#define BK 16

template<int EPI>
__global__ __launch_bounds__(256)
void mma_gemm(const float* __restrict__ A, const float* __restrict__ Wt,
              const float* __restrict__ bias, const float* __restrict__ res,
              float* __restrict__ C, int M, int N, int K) {
    __shared__ float As[BK][BM + 4];   // [k][m], tf32-rounded
    __shared__ float Bs[BK][BN + 4];   // [k][n], tf32-rounded

    const int tid  = threadIdx.x;
    const int lane = tid & 31;
    const int warp = tid >> 5;
    const int wm = warp >> 1;          // 0..3 (M dir)
    const int wn = warp & 1;           // 0..1 (N dir)
    const int m0 = blockIdx.y * BM;
    const int n0 = blockIdx.x * BN;

    // A staging: 128 rows x 16 cols fp32 = 512 float4; 2 per thread
    const int ar0 = tid >> 2;            // rows 0..63 (then +64)
    const int ak  = (tid & 3) * 4;
    // B staging: 16 x 64 = 256 float4; 1 per thread
    const int bk  = tid >> 4;
    const int bn  = (tid & 15) * 4;

    float acc[2][4][4];
#pragma unroll
    for (int i = 0; i < 2; i++)
#pragma unroll
        for (int j = 0; j < 4; j++)
#pragma unroll
            for (int t = 0; t < 4; t++) acc[i][j][t] = 0.f;

    const int gr = lane >> 2;       // 0..7 group row
    const int gc = lane & 3;        // 0..3 group col

    for (int k0 = 0; k0 < K; k0 += BK) {
#pragma unroll
        for (int h = 0; h < 2; h++) {
            int row = ar0 + h*64;
            float4 a4 = *(const float4*)(A + (size_t)(m0 + row)*K + k0 + ak);
            As[ak+0][row] = to_tf32(a4.x);
            As[ak+1][row] = to_tf32(a4.y);
            As[ak+2][row] = to_tf32(a4.z);
            As[ak+3][row] = to_tf32(a4.w);
        }
        {
            float4 b4 = make_float4(0.f,0.f,0.f,0.f);
            if (n0 + bn < N)
                b4 = *(const float4*)(Wt + (size_t)(k0 + bk)*N + n0 + bn);
            Bs[bk][bn+0] = to_tf32(b4.x);
            Bs[bk][bn+1] = to_tf32(b4.y);
            Bs[bk][bn+2] = to_tf32(b4.z);
            Bs[bk][bn+3] = to_tf32(b4.w);
        }
        __syncthreads();

#pragma unroll
        for (int ks = 0; ks < 2; ks++) {
            const int kb = ks * 8;
            // load B fragments: 4 n-tiles of n8k8
            unsigned bf[4][2];
#pragma unroll
            for (int nt = 0; nt < 4; nt++) {
                int ncol = wn*32 + nt*8 + gr;
                bf[nt][0] = __float_as_uint(Bs[kb + gc    ][ncol]);
                bf[nt][1] = __float_as_uint(Bs[kb + gc + 4][ncol]);
            }
            // load A fragments: 2 m-tiles of m16k8
            unsigned af[2][4];
#pragma unroll
            for (int mt = 0; mt < 2; mt++) {
                int mrow = wm*32 + mt*16 + gr;
                af[mt][0] = __float_as_uint(As[kb + gc    ][mrow    ]);
                af[mt][1] = __float_as_uint(As[kb + gc    ][mrow + 8]);
                af[mt][2] = __float_as_uint(As[kb + gc + 4][mrow    ]);
                af[mt][3] = __float_as_uint(As[kb + gc + 4][mrow + 8]);
            }
#pragma unroll
            for (int mt = 0; mt < 2; mt++)
#pragma unroll
                for (int nt = 0; nt < 4; nt++) {
                    asm volatile(
                        "mma.sync.aligned.m16n8k8.row.col.f32.tf32.tf32.f32 "
                        "{%0,%1,%2,%3}, {%4,%5,%6,%7}, {%8,%9}, {%0,%1,%2,%3};"
                        : "+f"(acc[mt][nt][0]), "+f"(acc[mt][nt][1]),
                          "+f"(acc[mt][nt][2]), "+f"(acc[mt][nt][3])
                        : "r"(af[mt][0]), "r"(af[mt][1]), "r"(af[mt][2]), "r"(af[mt][3]),
                          "r"(bf[nt][0]), "r"(bf[nt][1]));
                }
        }
        __syncthreads();
    }

    // epilogue: c0,c1 at (row, col0+0/1); c2,c3 at (row+8, col0+0/1)
#pragma unroll
    for (int mt = 0; mt < 2; mt++) {
#pragma unroll
        for (int nt = 0; nt < 4; nt++) {
            int col = n0 + wn*32 + nt*8 + gc*2;
            if (col < N) {
#pragma unroll
                for (int hh = 0; hh < 2; hh++) {
                    int row = m0 + wm*32 + mt*16 + gr + hh*8;
                    float v0 = acc[mt][nt][hh*2+0];
                    float v1 = acc[mt][nt][hh*2+1];
                    if (EPI >= 1) { v0 += bias[col]; v1 += bias[col+1]; }
                    if (EPI == 2) { v0 = gelu_exact(v0); v1 = gelu_exact(v1); }
                    if (EPI == 3) {
                        const float* rr = res + (size_t)row*N + col;
                        v0 += rr[0]; v1 += rr[1];
                    }
                    *(float2*)(C + (size_t)row*N + col) = make_float2(v0, v1);
                }
            }
        }
    }
}

// ---------------- fused windowed attention ----------------
__global__ __launch_bounds__(384)
void attn_kernel(const float* __restrict__ qbuf, const float* __restrict__ kvbuf,
                 const float* __restrict__ bias_table, float* __restrict__ aw) {
    __shared__ float sk[NHEADS*16*32];
    __shared__ float sv[NHEADS*16*32];
    const int wid = blockIdx.x;
    const int b  = wid >> 10;
    const int wy = (wid >> 5) & 31;
    const int wx = wid & 31;
    const int base = b*65536 + wy*8*256 + wx*8;
    const int tid = threadIdx.x;

    for (int ii = tid; ii < 2*16*192; ii += 384) {
        int sel = ii / (16*192);
        int rem = ii - sel*(16*192);
        int tok = rem / 192;
        int hd  = rem - tok*192;
        int i   = hd / 96;
        int j   = (hd / 48) & 1;
        int c48 = hd % 48;
        int p1 = tok >> 2, p2 = tok & 3;
        int grow = base + (p1*2 + i)*256 + (p2*2 + j);
        float val = kvbuf[(size_t)grow*96 + sel*48 + c48];
        float* dst = sel ? sv : sk;
        dst[(hd >> 5)*512 + tok*32 + (hd & 31)] = val;
    }
    __syncthreads();

    const int h  = tid / 64;
    const int qt = tid % 64;
    const int qr = qt >> 3, qc = qt & 7;
    const int qrow = base + qr*256 + qc;

    float q[32];
    const float* qp = qbuf + (size_t)qrow*Cc + h*32;
#pragma unroll
    for (int d4 = 0; d4 < 8; d4++) {
        float4 t = *(const float4*)(qp + d4*4);
        q[d4*4+0]=t.x; q[d4*4+1]=t.y; q[d4*4+2]=t.z; q[d4*4+3]=t.w;
    }

    const float SCALE = 0.17677669529663687f;
    const int qr2 = qr >> 1, qc2 = qc >> 1;
    float sc[16];
    float m = -1e30f;
#pragma unroll
    for (int kv = 0; kv < 16; kv++) {
        const float* kp = sk + h*512 + kv*32;
        float dot = 0.f;
#pragma unroll
        for (int d = 0; d < 32; d++) dot += q[d]*kp[d];
        int kr = kv >> 2, kc = kv & 3;
        int rel = (qr2 - kr + 3)*7 + (qc2 - kc + 3);
        float s = dot*SCALE + bias_table[rel*NHEADS + h];
        sc[kv] = s;
        m = fmaxf(m, s);
    }
    float sum = 0.f;
#pragma unroll
    for (int kv = 0; kv < 16; kv++) { sc[kv] = expf(sc[kv]-m); sum += sc[kv]; }
    float inv = 1.f/sum;
    float o[32];
#pragma unroll
    for (int d = 0; d < 32; d++) o[d] = 0.f;
#pragma unroll
    for (int kv = 0; kv < 16; kv++) {
        float p = sc[kv]*inv;
        const float* vp = sv + h*512 + kv*32;
#pragma unroll
        for (int d = 0; d < 32; d++) o[d] += p*vp[d];
    }
    float* op = aw + (size_t)qrow*Cc + h*32;
#pragma unroll
    for (int d4 = 0; d4 < 8; d4++) {
        *(float4*)(op + d4*4) = make_float4(o[d4*4+0],o[d4*4+1],o[d4*4+2],o[d4*4+3]);
    }
}

// ---------------- depthwise 5x5 conv branch ----------------
__global__ __launch_bounds__(256)
void dwconv_kernel(const float* __restrict__ h1, const float* __restrict__ dwk,
                   const float* __restrict__ dwb, float* __restrict__ out) {
    __shared__ float2 s[144][32];
    const int cb = blockIdx.z % 12;
    const int b  = blockIdx.z / 12;
    const int y0 = blockIdx.y * 8, x0 = blockIdx.x * 8;
    const int tid = threadIdx.x;

    for (int ii = tid; ii < 144*32; ii += 256) {
        int pix = ii >> 5, c2 = ii & 31;
        int py = pix / 12, px = pix % 12;
        int gy = y0 + py - 2, gx = x0 + px - 2;
        float2 v = make_float2(0.f, 0.f);
        if (gy >= 0 && gy < Hdim && gx >= 0 && gx < Wdim) {
            size_t row = (size_t)(b*65536 + gy*256 + gx);
            v = *(const float2*)(h1 + row*HID + cb*64 + c2*2);
        }
        s[pix][c2] = v;
    }
    __syncthreads();

    const int c2 = tid & 31;
    const int pq = tid >> 5;
    const int c0 = cb*64 + c2*2;

    float2 wk[25];
#pragma unroll
    for (int t = 0; t < 25; t++) {
        wk[t].x = dwk[(size_t)c0*25 + t];
        wk[t].y = dwk[(size_t)(c0+1)*25 + t];
    }
    float2 bb = make_float2(dwb[c0], dwb[c0+1]);

    float2 win[5][5];
#pragma unroll
    for (int dx = 0; dx < 5; dx++)
#pragma unroll
        for (int dy = 0; dy < 5; dy++)
            win[dx][dy] = s[(pq+dy)*12 + dx][c2];

#pragma unroll
    for (int px = 0; px < 8; px++) {
        float2 acc = make_float2(0.f, 0.f);
#pragma unroll
        for (int dy = 0; dy < 5; dy++)
#pragma unroll
            for (int dx = 0; dx < 5; dx++) {
                float2 v = win[dx][dy];
                float2 w = wk[dy*5+dx];
                acc.x += v.x*w.x;
                acc.y += v.y*w.y;
            }
        float2 center = win[2][2];
        float2 r;
        r.x = center.x + gelu_exact(acc.x + bb.x);
        r.y = center.y + gelu_exact(acc.y + bb.y);
        size_t row = (size_t)(b*65536 + (y0+pq)*256 + (x0+px));
        *(float2*)(out + row*HID + c0) = r;
        if (px < 7) {
#pragma unroll
            for (int dx = 0; dx < 4; dx++)
#pragma unroll
                for (int dy = 0; dy < 5; dy++)
                    win[dx][dy] = win[dx+1][dy];
#pragma unroll
            for (int dy = 0; dy < 5; dy++)
                win[4][dy] = s[(pq+dy)*12 + (px+5)][c2];
        }
    }
}

// ---------------- launch ----------------
extern "C" void kernel_launch(void* const* d_in, const int* in_sizes, int n_in,
                              void* d_out, int out_size) {
    const float* x          = (const float*)d_in[0];
    const float* g1         = (const float*)d_in[1];
    const float* be1        = (const float*)d_in[2];
    const float* wq         = (const float*)d_in[3];
    const float* bq         = (const float*)d_in[4];
    const float* wkv        = (const float*)d_in[5];
    const float* bkv        = (const float*)d_in[6];
    const float* bias_table = (const float*)d_in[7];
    const float* wproj      = (const float*)d_in[8];
    const float* bproj      = (const float*)d_in[9];
    const float* g2         = (const float*)d_in[10];
    const float* be2        = (const float*)d_in[11];
    const float* w1f        = (const float*)d_in[12];
    const float* b1f        = (const float*)d_in[13];
    const float* dwk        = (const float*)d_in[14];
    const float* dwb        = (const float*)d_in[15];
    const float* w2f        = (const float*)d_in[16];
    const float* b2f        = (const float*)d_in[17];
    float* out = (float*)d_out;

    float *bufA, *bufB, *bufC, *bufD, *bufE;
    cudaGetSymbolAddress((void**)&bufA, g_bufA);
    cudaGetSymbolAddress((void**)&bufB, g_bufB);
    cudaGetSymbolAddress((void**)&bufC, g_bufC);
    cudaGetSymbolAddress((void**)&bufD, g_bufD);
    cudaGetSymbolAddress((void**)&bufE, g_bufE);

    // 1. LN1
    ln_kernel<<<TOK/8, 256>>>(x, g1, be1, bufA);
    // 2. q = xn @ wq + bq
    mma_gemm<1><<<dim3(3, TOK/BM), 256>>>(bufA, wq, bq, nullptr, bufD, TOK, 192, 192);
    // 3. kv = xn @ wkv + bkv
    mma_gemm<1><<<dim3(2, TOK/BM), 256>>>(bufA, wkv, bkv, nullptr, bufE, TOK, 96, 192);
    // 4. attention
    attn_kernel<<<NWIN, 384>>>(bufD, bufE, bias_table, bufB);
    // 5. x2 = x + aw @ wproj + bproj
    mma_gemm<3><<<dim3(3, TOK/BM), 256>>>(bufB, wproj, bproj, x, bufC, TOK, 192, 192);
    // 6. LN2
    ln_kernel<<<TOK/8, 256>>>(bufC, g2, be2, bufA);
    // 7. h1 = gelu(xn2 @ w1f + b1f)
    mma_gemm<2><<<dim3(12, TOK/BM), 256>>>(bufA, w1f, b1f, nullptr, bufD, TOK, HID, 192);
    // 8. dwconv branch
    dwconv_kernel<<<dim3(32, 32, Bsz*12), 256>>>(bufD, dwk, dwb, bufE);
    // 9. out = x2 + h @ w2f + b2f
    mma_gemm<3><<<dim3(3, TOK/BM), 256>>>(bufE, w2f, b2f, bufC, out, TOK, 192, HID);
}

// round 3
// speedup vs baseline: 1.8862x; 1.1895x over previous
#include <cuda_runtime.h>
#include <math.h>
#include <stdint.h>

// ---------------- problem constants ----------------
#define Bsz     2
#define Hdim    256
#define Wdim    256
#define Cc      192
#define NHEADS  6
#define HID     768
#define TOK     (Bsz*Hdim*Wdim)      // 131072 tokens
#define NWIN    2048

// ---------------- scratch ----------------
__device__ float g_bufA[(size_t)TOK*Cc];
__device__ float g_bufB[(size_t)TOK*Cc];
__device__ float g_bufC[(size_t)TOK*Cc];
__device__ float g_bufD[(size_t)TOK*HID];
__device__ float g_bufE[(size_t)TOK*HID];

__device__ __forceinline__ float gelu_exact(float x) {
    return 0.5f * x * (1.0f + erff(x * 0.70710678118654752f));
}

__device__ __forceinline__ void cp_async16(uint32_t dst, const void* src, int srcsize) {
    asm volatile("cp.async.cg.shared.global [%0], [%1], 16, %2;"
                 :: "r"(dst), "l"(src), "r"(srcsize));
}
__device__ __forceinline__ void cp_commit() {
    asm volatile("cp.async.commit_group;");
}
template<int N_>
__device__ __forceinline__ void cp_wait() {
    asm volatile("cp.async.wait_group %0;" :: "n"(N_));
}

// ---------------- LayerNorm ----------------
__global__ __launch_bounds__(256)
void ln_kernel(const float* __restrict__ x, const float* __restrict__ g,
               const float* __restrict__ b, float* __restrict__ out) {
    int warp = (blockIdx.x * blockDim.x + threadIdx.x) >> 5;
    int lane = threadIdx.x & 31;
    if (warp >= TOK) return;
    const float* xr = x + (size_t)warp * Cc;
    float v[6];
    float s = 0.f, s2 = 0.f;
#pragma unroll
    for (int j = 0; j < 6; j++) {
        v[j] = xr[lane + 32*j];
        s += v[j]; s2 += v[j]*v[j];
    }
#pragma unroll
    for (int o = 16; o; o >>= 1) {
        s  += __shfl_xor_sync(0xffffffffu, s,  o);
        s2 += __shfl_xor_sync(0xffffffffu, s2, o);
    }
    float mu  = s  * (1.f/Cc);
    float var = s2 * (1.f/Cc) - mu*mu;
    float r   = rsqrtf(var + 1e-5f);
    float* orow = out + (size_t)warp * Cc;
#pragma unroll
    for (int j = 0; j < 6; j++) {
        int c = lane + 32*j;
        orow[c] = (v[j]-mu)*r*g[c] + b[c];
    }
}

// ---------------- tf32 tensor-core GEMM, cp.async 2-stage pipeline ----------------
// C[M,N] = A[M,K] @ W[K,N]  (+bias)(+gelu)(+res)
// Tile 128x128x16, 256 threads (8 warps as 2x4), warp tile 64x32.
// fp32 bits fed directly to tf32 mma (hw truncation).
// EPI: 1=bias, 2=bias+gelu, 3=bias+residual
#define BM 128
#define BN 128
#define BK 16

template<int EPI>
__global__ __launch_bounds__(256)
void mma_gemm(const float* __restrict__ A, const float* __restrict__ Wt,
              const float* __restrict__ bias, const float* __restrict__ res,
              float* __restrict__ C, int M, int N, int K) {
    __shared__ float As[2][BM][20];    // [m][k], stride 20 -> conflict-free frag loads
    __shared__ float Bs[2][BK][136];   // [k][n], stride 136

    const int tid  = threadIdx.x;
    const int lane = tid & 31;
    const int warp = tid >> 5;
    const int wm = (warp >> 2) * 64;   // 0 / 64
    const int wn = (warp & 3) * 32;    // 0..96
    const int m0 = blockIdx.y * BM;
    const int n0 = blockIdx.x * BN;
    const int gr = lane >> 2;          // 0..7
    const int gc = lane & 3;           // 0..3

    uint32_t as_base = (uint32_t)__cvta_generic_to_shared(&As[0][0][0]);
    uint32_t bs_base = (uint32_t)__cvta_generic_to_shared(&Bs[0][0][0]);

    float acc[4][4][4];
#pragma unroll
    for (int i = 0; i < 4; i++)
#pragma unroll
        for (int j = 0; j < 4; j++)
#pragma unroll
            for (int t = 0; t < 4; t++) acc[i][j][t] = 0.f;

    const int niter = K / BK;

    // ---- staging helper (2 float4 for A, 2 float4 for B per thread) ----
    auto load_stage = [&](int s, int k0) {
#pragma unroll
        for (int h = 0; h < 2; h++) {
            int f  = tid + h*256;          // 0..511
            int m  = f >> 2;               // 0..127
            int kc = (f & 3) * 4;          // 0,4,8,12
            uint32_t dst = as_base + (uint32_t)(((s*BM + m)*20 + kc) * 4);
            const float* src = A + (size_t)(m0 + m)*K + k0 + kc;
            cp_async16(dst, src, 16);
        }
#pragma unroll
        for (int h = 0; h < 2; h++) {
            int f  = tid + h*256;
            int k  = f >> 5;               // 0..15
            int n4 = (f & 31) * 4;         // 0..124
            uint32_t dst = bs_base + (uint32_t)(((s*BK + k)*136 + n4) * 4);
            int col = n0 + n4;
            const float* src = Wt + (size_t)(k0 + k)*N + (col < N ? col : 0);
            cp_async16(dst, src, col < N ? 16 : 0);
        }
    };

    load_stage(0, 0);
    cp_commit();

    for (int it = 0; it < niter; it++) {
        if (it + 1 < niter) load_stage((it + 1) & 1, (it + 1) * BK);
        cp_commit();
        cp_wait<1>();
        __syncthreads();

        const int s = it & 1;
#pragma unroll
        for (int ks = 0; ks < 2; ks++) {
            const int kb = ks * 8;
            unsigned af[4][4];
#pragma unroll
            for (int mt = 0; mt < 4; mt++) {
                int mr = wm + mt*16 + gr;
                af[mt][0] = __float_as_uint(As[s][mr    ][kb + gc    ]);
                af[mt][1] = __float_as_uint(As[s][mr + 8][kb + gc    ]);
                af[mt][2] = __float_as_uint(As[s][mr    ][kb + gc + 4]);
                af[mt][3] = __float_as_uint(As[s][mr + 8][kb + gc + 4]);
            }
            unsigned bf[4][2];
#pragma unroll
            for (int nt = 0; nt < 4; nt++) {
                int nc = wn + nt*8 + gr;
                bf[nt][0] = __float_as_uint(Bs[s][kb + gc    ][nc]);
                bf[nt][1] = __float_as_uint(Bs[s][kb + gc + 4][nc]);
            }
#pragma unroll
            for (int mt = 0; mt < 4; mt++)
#pragma unroll
                for (int nt = 0; nt < 4; nt++) {
                    asm volatile(
                        "mma.sync.aligned.m16n8k8.row.col.f32.tf32.tf32.f32 "
                        "{%0,%1,%2,%3}, {%4,%5,%6,%7}, {%8,%9}, {%0,%1,%2,%3};"
                        : "+f"(acc[mt][nt][0]), "+f"(acc[mt][nt][1]),
                          "+f"(acc[mt][nt][2]), "+f"(acc[mt][nt][3])
                        : "r"(af[mt][0]), "r"(af[mt][1]), "r"(af[mt][2]), "r"(af[mt][3]),
                          "r"(bf[nt][0]), "r"(bf[nt][1]));
                }
        }
        __syncthreads();
    }

    // ---- epilogue ----
#pragma unroll
    for (int mt = 0; mt < 4; mt++) {
#pragma unroll
        for (int nt = 0; nt < 4; nt++) {
            int col = n0 + wn + nt*8 + gc*2;
            if (col < N) {
#pragma unroll
                for (int hh = 0; hh < 2; hh++) {
                    int row = m0 + wm + mt*16 + gr + hh*8;
                    float v0 = acc[mt][nt][hh*2+0];
                    float v1 = acc[mt][nt][hh*2+1];
                    if (EPI >= 1) { v0 += bias[col]; v1 += bias[col+1]; }
                    if (EPI == 2) { v0 = gelu_exact(v0); v1 = gelu_exact(v1); }
                    if (EPI == 3) {
                        const float* rr = res + (size_t)row*N + col;
                        v0 += rr[0]; v1 += rr[1];
                    }
                    *(float2*)(C + (size_t)row*N + col) = make_float2(v0, v1);
                }
            }
        }
    }
}

// ---------------- fused windowed attention ----------------
__global__ __launch_bounds__(384)
void attn_kernel(const float* __restrict__ qbuf, const float* __restrict__ kvbuf,
                 const float* __restrict__ bias_table, float* __restrict__ aw) {
    __shared__ float sk[NHEADS*16*32];
    __shared__ float sv[NHEADS*16*32];
    const int wid = blockIdx.x;
    const int b  = wid >> 10;
    const int wy = (wid >> 5) & 31;
    const int wx = wid & 31;
    const int base = b*65536 + wy*8*256 + wx*8;
    const int tid = threadIdx.x;

    for (int ii = tid; ii < 2*16*192; ii += 384) {
        int sel = ii / (16*192);
        int rem = ii - sel*(16*192);
        int tok = rem / 192;
        int hd  = rem - tok*192;
        int i   = hd / 96;
        int j   = (hd / 48) & 1;
        int c48 = hd % 48;
        int p1 = tok >> 2, p2 = tok & 3;
        int grow = base + (p1*2 + i)*256 + (p2*2 + j);
        float val = kvbuf[(size_t)grow*96 + sel*48 + c48];
        float* dst = sel ? sv : sk;
        dst[(hd >> 5)*512 + tok*32 + (hd & 31)] = val;
    }
    __syncthreads();

    const int h  = tid / 64;
    const int qt = tid % 64;
    const int qr = qt >> 3, qc = qt & 7;
    const int qrow = base + qr*256 + qc;

    float q[32];
    const float* qp = qbuf + (size_t)qrow*Cc + h*32;
#pragma unroll
    for (int d4 = 0; d4 < 8; d4++) {
        float4 t = *(const float4*)(qp + d4*4);
        q[d4*4+0]=t.x; q[d4*4+1]=t.y; q[d4*4+2]=t.z; q[d4*4+3]=t.w;
    }

    const float SCALE = 0.17677669529663687f;
    const int qr2 = qr >> 1, qc2 = qc >> 1;
    float sc[16];
    float m = -1e30f;
#pragma unroll
    for (int kv = 0; kv < 16; kv++) {
        const float* kp = sk + h*512 + kv*32;
        float dot = 0.f;
#pragma unroll
        for (int d = 0; d < 32; d++) dot += q[d]*kp[d];
        int kr = kv >> 2, kc = kv & 3;
        int rel = (qr2 - kr + 3)*7 + (qc2 - kc + 3);
        float s = dot*SCALE + bias_table[rel*NHEADS + h];
        sc[kv] = s;
        m = fmaxf(m, s);
    }
    float sum = 0.f;
#pragma unroll
    for (int kv = 0; kv < 16; kv++) { sc[kv] = expf(sc[kv]-m); sum += sc[kv]; }
    float inv = 1.f/sum;
    float o[32];
#pragma unroll
    for (int d = 0; d < 32; d++) o[d] = 0.f;
#pragma unroll
    for (int kv = 0; kv < 16; kv++) {
        float p = sc[kv]*inv;
        const float* vp = sv + h*512 + kv*32;
#pragma unroll
        for (int d = 0; d < 32; d++) o[d] += p*vp[d];
    }
    float* op = aw + (size_t)qrow*Cc + h*32;
#pragma unroll
    for (int d4 = 0; d4 < 8; d4++) {
        *(float4*)(op + d4*4) = make_float4(o[d4*4+0],o[d4*4+1],o[d4*4+2],o[d4*4+3]);
    }
}

// ---------------- depthwise 5x5 conv branch ----------------
__global__ __launch_bounds__(256)
void dwconv_kernel(const float* __restrict__ h1, const float* __restrict__ dwk,
                   const float* __restrict__ dwb, float* __restrict__ out) {
    __shared__ float2 s[144][32];
    const int cb = blockIdx.z % 12;
    const int b  = blockIdx.z / 12;
    const int y0 = blockIdx.y * 8, x0 = blockIdx.x * 8;
    const int tid = threadIdx.x;

    for (int ii = tid; ii < 144*32; ii += 256) {
        int pix = ii >> 5, c2 = ii & 31;
        int py = pix / 12, px = pix % 12;
        int gy = y0 + py - 2, gx = x0 + px - 2;
        float2 v = make_float2(0.f, 0.f);
        if (gy >= 0 && gy < Hdim && gx >= 0 && gx < Wdim) {
            size_t row = (size_t)(b*65536 + gy*256 + gx);
            v = *(const float2*)(h1 + row*HID + cb*64 + c2*2);
        }
        s[pix][c2] = v;
    }
    __syncthreads();

    const int c2 = tid & 31;
    const int pq = tid >> 5;
    const int c0 = cb*64 + c2*2;

    float2 wk[25];
#pragma unroll
    for (int t = 0; t < 25; t++) {
        wk[t].x = dwk[(size_t)c0*25 + t];
        wk[t].y = dwk[(size_t)(c0+1)*25 + t];
    }
    float2 bb = make_float2(dwb[c0], dwb[c0+1]);

    float2 win[5][5];
#pragma unroll
    for (int dx = 0; dx < 5; dx++)
#pragma unroll
        for (int dy = 0; dy < 5; dy++)
            win[dx][dy] = s[(pq+dy)*12 + dx][c2];

#pragma unroll
    for (int px = 0; px < 8; px++) {
        float2 acc = make_float2(0.f, 0.f);
#pragma unroll
        for (int dy = 0; dy < 5; dy++)
#pragma unroll
            for (int dx = 0; dx < 5; dx++) {
                float2 v = win[dx][dy];
                float2 w = wk[dy*5+dx];
                acc.x += v.x*w.x;
                acc.y += v.y*w.y;
            }
        float2 center = win[2][2];
        float2 r;
        r.x = center.x + gelu_exact(acc.x + bb.x);
        r.y = center.y + gelu_exact(acc.y + bb.y);
        size_t row = (size_t)(b*65536 + (y0+pq)*256 + (x0+px));
        *(float2*)(out + row*HID + c0) = r;
        if (px < 7) {
#pragma unroll
            for (int dx = 0; dx < 4; dx++)
#pragma unroll
                for (int dy = 0; dy < 5; dy++)
                    win[dx][dy] = win[dx+1][dy];
#pragma unroll
            for (int dy = 0; dy < 5; dy++)
                win[4][dy] = s[(pq+dy)*12 + (px+5)][c2];
        }
    }
}

// ---------------- launch ----------------
extern "C" void kernel_launch(void* const* d_in, const int* in_sizes, int n_in,
                              void* d_out, int out_size) {
    const float* x          = (const float*)d_in[0];
    const float* g1         = (const float*)d_in[1];
    const float* be1        = (const float*)d_in[2];
    const float* wq         = (const float*)d_in[3];
    const float* bq         = (const float*)d_in[4];
    const float* wkv        = (const float*)d_in[5];
    const float* bkv        = (const float*)d_in[6];
    const float* bias_table = (const float*)d_in[7];
    const float* wproj      = (const float*)d_in[8];
    const float* bproj      = (const float*)d_in[9];
    const float* g2         = (const float*)d_in[10];
    const float* be2        = (const float*)d_in[11];
    const float* w1f        = (const float*)d_in[12];
    const float* b1f        = (const float*)d_in[13];
    const float* dwk        = (const float*)d_in[14];
    const float* dwb        = (const float*)d_in[15];
    const float* w2f        = (const float*)d_in[16];
    const float* b2f        = (const float*)d_in[17];
    float* out = (float*)d_out;

    float *bufA, *bufB, *bufC, *bufD, *bufE;
    cudaGetSymbolAddress((void**)&bufA, g_bufA);
    cudaGetSymbolAddress((void**)&bufB, g_bufB);
    cudaGetSymbolAddress((void**)&bufC, g_bufC);
    cudaGetSymbolAddress((void**)&bufD, g_bufD);
    cudaGetSymbolAddress((void**)&bufE, g_bufE);

    // 1. LN1
    ln_kernel<<<TOK/8, 256>>>(x, g1, be1, bufA);
    // 2. q = xn @ wq + bq      (N=192 -> 2 n-blocks)
    mma_gemm<1><<<dim3(2, TOK/BM), 256>>>(bufA, wq, bq, nullptr, bufD, TOK, 192, 192);
    // 3. kv = xn @ wkv + bkv   (N=96 -> 1 n-block)
    mma_gemm<1><<<dim3(1, TOK/BM), 256>>>(bufA, wkv, bkv, nullptr, bufE, TOK, 96, 192);
    // 4. attention
    attn_kernel<<<NWIN, 384>>>(bufD, bufE, bias_table, bufB);
    // 5. x2 = x + aw @ wproj + bproj
    mma_gemm<3><<<dim3(2, TOK/BM), 256>>>(bufB, wproj, bproj, x, bufC, TOK, 192, 192);
    // 6. LN2
    ln_kernel<<<TOK/8, 256>>>(bufC, g2, be2, bufA);
    // 7. h1 = gelu(xn2 @ w1f + b1f)
    mma_gemm<2><<<dim3(6, TOK/BM), 256>>>(bufA, w1f, b1f, nullptr, bufD, TOK, HID, 192);
    // 8. dwconv branch
    dwconv_kernel<<<dim3(32, 32, Bsz*12), 256>>>(bufD, dwk, dwb, bufE);
    // 9. out = x2 + h @ w2f + b2f
    mma_gemm<3><<<dim3(2, TOK/BM), 256>>>(bufE, w2f, b2f, bufC, out, TOK, 192, HID);
}